// round 12
// baseline (speedup 1.0000x reference)
#include <cuda_runtime.h>
#include <cuda_fp16.h>

#define NMAX 100000
#define EMAX 3200000
#define DD 64
#define SCAN_B 1024

// Scratch (device globals; allocation is forbidden)
// Layer-1 CSR set
__device__ float  g_dinv[NMAX];
__device__ int    g_cnt[NMAX];
__device__ int    g_off[NMAX];
__device__ int    g_cur[NMAX];
__device__ int    g_csr[EMAX];
__device__ int    g_tot[1];
// Layer-2 CSR set (built concurrently on a forked stream)
__device__ float  g_dinv2[NMAX];
__device__ int    g_cnt2[NMAX];
__device__ int    g_off2[NMAX];
__device__ int    g_cur2[NMAX];
__device__ int    g_csr2[EMAX];
__device__ int    g_tot2[1];

__device__ float  g_h[NMAX * DD];      // layer-1 X@W1 (pre-epilogue)
__device__ __half2 g_hsh[NMAX * 32];   // h*dinv[row], fp16, 32 half2 per row
__device__ float  g_agg[NMAX * DD];    // layer-1 output (self+bias, then += messages)

// ---------------------------------------------------------------------------
__global__ void k_count(const int* __restrict__ dst, int* __restrict__ cnt, int ne) {
    int i = blockIdx.x * blockDim.x + threadIdx.x;
    if (i < ne) atomicAdd(cnt + dst[i], 1);   // no return -> RED
}

// Fused scan: per-block prefix + atomic block base (CSR ranges need only be
// disjoint, not monotonic in node id). Also emits cur copy + dinv.
__global__ void k_scanA(const int* __restrict__ cnt, int* __restrict__ off,
                        int* __restrict__ cur, float* __restrict__ dinv,
                        int* __restrict__ tot, int n) {
    __shared__ int sh[SCAN_B];
    __shared__ int base_sh;
    int i = blockIdx.x * SCAN_B + threadIdx.x;
    int v = (i < n) ? cnt[i] : 0;
    sh[threadIdx.x] = v;
    __syncthreads();
#pragma unroll
    for (int d = 1; d < SCAN_B; d <<= 1) {
        int t = (threadIdx.x >= d) ? sh[threadIdx.x - d] : 0;
        __syncthreads();
        sh[threadIdx.x] += t;
        __syncthreads();
    }
    if (threadIdx.x == SCAN_B - 1) base_sh = atomicAdd(tot, sh[SCAN_B - 1]);
    __syncthreads();
    if (i < n) {
        int o = base_sh + sh[threadIdx.x] - v;
        off[i] = o;
        cur[i] = o;
        dinv[i] = rsqrtf((float)v + 1.0f);
    }
}

__global__ void k_fill(const int* __restrict__ src, const int* __restrict__ dst,
                       int* __restrict__ cur, int* __restrict__ csr, int ne) {
    int i = blockIdx.x * blockDim.x + threadIdx.x;
    if (i < ne) {
        int p = atomicAdd(cur + dst[i], 1);
        csr[p] = src[i];
    }
}

// ---------------------------------------------------------------------------
// Register-tiled GEMM.  fuse=0: out_h = f(in)@W only.
// fuse=1: additionally hsh = fp16(h*dinv), agg = h*dinv^2 + b.
#define XPAD 68
__global__ __launch_bounds__(256, 2)
void k_gemm_fused(const float* __restrict__ in, const float* __restrict__ W,
                  const float* __restrict__ b, const float* __restrict__ dinv,
                  __half2* __restrict__ hsh, float* __restrict__ agg,
                  int n, int do_relu, int fuse) {
    extern __shared__ float smem_f[];
    float* Ws = smem_f;                 // 64*64
    float* xs = smem_f + DD * DD;       // 256*XPAD

    int tid = threadIdx.x;
    int cx = tid & 15;
    int ry = tid >> 4;
    int row0 = blockIdx.x * 256;

    for (int i = tid; i < DD * DD; i += 256) Ws[i] = W[i];

    for (int i = tid; i < 256 * 16; i += 256) {
        int r = i >> 4, c4 = i & 15;
        int grow = row0 + r;
        float4 v = make_float4(0.f, 0.f, 0.f, 0.f);
        if (grow < n) v = __ldg(reinterpret_cast<const float4*>(in + (size_t)grow * DD) + c4);
        if (do_relu) {
            v.x = fmaxf(v.x, 0.f); v.y = fmaxf(v.y, 0.f);
            v.z = fmaxf(v.z, 0.f); v.w = fmaxf(v.w, 0.f);
        }
        *reinterpret_cast<float4*>(&xs[r * XPAD + c4 * 4]) = v;
    }
    __syncthreads();

    float4 acc[16];
#pragma unroll
    for (int i = 0; i < 16; i++) acc[i] = make_float4(0.f, 0.f, 0.f, 0.f);

#pragma unroll
    for (int k4 = 0; k4 < 16; k4++) {
        float4 w0 = *reinterpret_cast<const float4*>(&Ws[(k4 * 4 + 0) * DD + cx * 4]);
        float4 w1 = *reinterpret_cast<const float4*>(&Ws[(k4 * 4 + 1) * DD + cx * 4]);
        float4 w2 = *reinterpret_cast<const float4*>(&Ws[(k4 * 4 + 2) * DD + cx * 4]);
        float4 w3 = *reinterpret_cast<const float4*>(&Ws[(k4 * 4 + 3) * DD + cx * 4]);
#pragma unroll
        for (int i = 0; i < 16; i++) {
            float4 xv = *reinterpret_cast<const float4*>(&xs[(ry + 16 * i) * XPAD + k4 * 4]);
            acc[i].x = fmaf(w0.x, xv.x, acc[i].x);
            acc[i].y = fmaf(w0.y, xv.x, acc[i].y);
            acc[i].z = fmaf(w0.z, xv.x, acc[i].z);
            acc[i].w = fmaf(w0.w, xv.x, acc[i].w);
            acc[i].x = fmaf(w1.x, xv.y, acc[i].x);
            acc[i].y = fmaf(w1.y, xv.y, acc[i].y);
            acc[i].z = fmaf(w1.z, xv.y, acc[i].z);
            acc[i].w = fmaf(w1.w, xv.y, acc[i].w);
            acc[i].x = fmaf(w2.x, xv.z, acc[i].x);
            acc[i].y = fmaf(w2.y, xv.z, acc[i].y);
            acc[i].z = fmaf(w2.z, xv.z, acc[i].z);
            acc[i].w = fmaf(w2.w, xv.z, acc[i].w);
            acc[i].x = fmaf(w3.x, xv.w, acc[i].x);
            acc[i].y = fmaf(w3.y, xv.w, acc[i].y);
            acc[i].z = fmaf(w3.z, xv.w, acc[i].z);
            acc[i].w = fmaf(w3.w, xv.w, acc[i].w);
        }
    }

    if (!fuse) {
#pragma unroll
        for (int i = 0; i < 16; i++) {
            int grow = row0 + ry + 16 * i;
            if (grow < n)
                *reinterpret_cast<float4*>(agg + (size_t)grow * DD + cx * 4) = acc[i];
        }
        return;
    }

    float4 bv = __ldg(reinterpret_cast<const float4*>(b) + cx);
#pragma unroll
    for (int i = 0; i < 16; i++) {
        int grow = row0 + ry + 16 * i;
        if (grow >= n) continue;
        float di = __ldg(dinv + grow);
        float4 h4 = acc[i];
        float4 hs4 = make_float4(h4.x * di, h4.y * di, h4.z * di, h4.w * di);
        float4 ag4 = make_float4(fmaf(hs4.x, di, bv.x), fmaf(hs4.y, di, bv.y),
                                 fmaf(hs4.z, di, bv.z), fmaf(hs4.w, di, bv.w));
        __half2 p0 = __floats2half2_rn(hs4.x, hs4.y);
        __half2 p1 = __floats2half2_rn(hs4.z, hs4.w);
        uint2 packed;
        packed.x = *reinterpret_cast<unsigned int*>(&p0);
        packed.y = *reinterpret_cast<unsigned int*>(&p1);
        *reinterpret_cast<uint2*>(hsh + (size_t)grow * 32 + cx * 2) = packed;
        *reinterpret_cast<float4*>(agg + (size_t)grow * DD + cx * 4) = ag4;
    }
}

// ---------------------------------------------------------------------------
// Standalone epilogue for layer 1 (lets GEMM overlap the CSR build):
//   hsh = fp16(h*dinv), agg = h*dinv^2 + b
__global__ __launch_bounds__(256)
void k_epilogue(const float* __restrict__ h, const float* __restrict__ dinv,
                const float* __restrict__ b, __half2* __restrict__ hsh,
                float* __restrict__ agg, int n) {
    int i = blockIdx.x * blockDim.x + threadIdx.x;
    if (i >= n * 16) return;
    int row = i >> 4, c4 = i & 15;
    float di = __ldg(dinv + row);
    float4 h4 = __ldg(reinterpret_cast<const float4*>(h) + i);
    float4 bv = __ldg(reinterpret_cast<const float4*>(b) + c4);
    float4 hs4 = make_float4(h4.x * di, h4.y * di, h4.z * di, h4.w * di);
    float4 ag4 = make_float4(fmaf(hs4.x, di, bv.x), fmaf(hs4.y, di, bv.y),
                             fmaf(hs4.z, di, bv.z), fmaf(hs4.w, di, bv.w));
    __half2 p0 = __floats2half2_rn(hs4.x, hs4.y);
    __half2 p1 = __floats2half2_rn(hs4.z, hs4.w);
    uint2 packed;
    packed.x = *reinterpret_cast<unsigned int*>(&p0);
    packed.y = *reinterpret_cast<unsigned int*>(&p1);
    *(reinterpret_cast<uint2*>(hsh + (size_t)row * 32) + c4) = packed;
    *(reinterpret_cast<float4*>(agg) + i) = ag4;
}

// ---------------------------------------------------------------------------
// Gather-by-destination: one warp per node; STATIC 16x2-edge unrolled chunk
// so ptxas can keep ~16 guarded loads in flight per lane (MLP >> 2).
// Half-warp h processes edges of parity h; lane sub owns cols [4*sub,4*sub+3].
__global__ __launch_bounds__(256)
void k_aggregate(const int* __restrict__ csr, const int* __restrict__ off,
                 const int* __restrict__ cnt, const float* __restrict__ dinv,
                 const __half2* __restrict__ hsh, float* __restrict__ out, int n) {
    int node = blockIdx.x * 8 + (threadIdx.x >> 5);
    int lane = threadIdx.x & 31;
    if (node >= n) return;

    const unsigned FULL = 0xffffffffu;
    int half = lane >> 4;
    int sub  = lane & 15;
    int beg = off[node];
    int m = cnt[node];
    float nd = dinv[node];

    float4 acc = make_float4(0.f, 0.f, 0.f, 0.f);

    for (int j = 0; j < m; j += 32) {
        int rem = m - j;
        int myidx = (lane < rem) ? __ldg(csr + beg + j + lane) : 0;
        int lim = rem < 32 ? rem : 32;
#pragma unroll
        for (int t = 0; t < 16; t++) {
            int eid = 2 * t + half;
            int s = __shfl_sync(FULL, myidx, eid);
            if (eid < lim) {
                uint2 v = __ldg(reinterpret_cast<const uint2*>(hsh + (size_t)s * 32) + sub);
                float2 f0 = __half22float2(*reinterpret_cast<__half2*>(&v.x));
                float2 f1 = __half22float2(*reinterpret_cast<__half2*>(&v.y));
                acc.x += f0.x; acc.y += f0.y; acc.z += f1.x; acc.w += f1.y;
            }
        }
    }

    acc.x += __shfl_xor_sync(FULL, acc.x, 16);
    acc.y += __shfl_xor_sync(FULL, acc.y, 16);
    acc.z += __shfl_xor_sync(FULL, acc.z, 16);
    acc.w += __shfl_xor_sync(FULL, acc.w, 16);

    if (half == 0) {
        float4* op = reinterpret_cast<float4*>(out + (size_t)node * DD + sub * 4);
        float4 o = *op;
        o.x = fmaf(acc.x, nd, o.x);
        o.y = fmaf(acc.y, nd, o.y);
        o.z = fmaf(acc.z, nd, o.z);
        o.w = fmaf(acc.w, nd, o.w);
        *op = o;
    }
}

// ---------------------------------------------------------------------------
static void* sym_addr(const void* sym) {
    void* p = nullptr;
    cudaGetSymbolAddress(&p, sym);
    return p;
}

extern "C" void kernel_launch(void* const* d_in, const int* in_sizes, int n_in,
                              void* d_out, int out_size) {
    const float* x  = (const float*)d_in[0];
    const float* W1 = (const float*)d_in[1];
    const float* b1 = (const float*)d_in[2];
    const float* W2 = (const float*)d_in[3];
    const float* b2 = (const float*)d_in[4];
    const int*   e0 = (const int*)d_in[5];   // [2, E]: src row then dst row
    const int*   e1 = (const int*)d_in[6];

    const int N = in_sizes[0] / DD;
    const int E = in_sizes[5] / 2;
    const int NB = (N + SCAN_B - 1) / SCAN_B;

    float*  dinv  = (float*)sym_addr(g_dinv);
    int*    cnt   = (int*)sym_addr(g_cnt);
    int*    off   = (int*)sym_addr(g_off);
    int*    cur   = (int*)sym_addr(g_cur);
    int*    csr   = (int*)sym_addr(g_csr);
    int*    tot   = (int*)sym_addr(g_tot);
    float*  dinv2 = (float*)sym_addr(g_dinv2);
    int*    cnt2  = (int*)sym_addr(g_cnt2);
    int*    off2  = (int*)sym_addr(g_off2);
    int*    cur2  = (int*)sym_addr(g_cur2);
    int*    csr2  = (int*)sym_addr(g_csr2);
    int*    tot2  = (int*)sym_addr(g_tot2);
    float*  h     = (float*)sym_addr(g_h);
    __half2* hsh  = (__half2*)sym_addr(g_hsh);
    float*  agg   = (float*)sym_addr(g_agg);
    float*  out   = (float*)d_out;

    const int T = 256;
    int e_grid  = (E + T - 1) / T;
    int ep_grid = (N * 16 + T - 1) / T;
    int ag_grid = (N + 7) / 8;
    int gm_grid = (N + 255) / 256;
    size_t gm_smem = (DD * DD + 256 * XPAD) * sizeof(float);

    static cudaStream_t sCsr1 = nullptr, sCsr2 = nullptr;
    static cudaEvent_t evFork, evCsr1, evCsr2;
    static int init_done = 0;
    if (!init_done) {
        cudaFuncSetAttribute(k_gemm_fused, cudaFuncAttributeMaxDynamicSharedMemorySize,
                             (int)gm_smem);
        cudaStreamCreateWithFlags(&sCsr1, cudaStreamNonBlocking);
        cudaStreamCreateWithFlags(&sCsr2, cudaStreamNonBlocking);
        cudaEventCreateWithFlags(&evFork, cudaEventDisableTiming);
        cudaEventCreateWithFlags(&evCsr1, cudaEventDisableTiming);
        cudaEventCreateWithFlags(&evCsr2, cudaEventDisableTiming);
        init_done = 1;
    }

    cudaEventRecord(evFork, 0);

    // -------- main: layer-1 GEMM (no dinv dependency) --------
    k_gemm_fused<<<gm_grid, 256, gm_smem>>>(x, W1, nullptr, nullptr, nullptr, h, N, 0, 0);

    // -------- sCsr1: layer-1 CSR build (overlaps gemm1) --------
    cudaStreamWaitEvent(sCsr1, evFork, 0);
    cudaMemsetAsync(cnt, 0, N * sizeof(int), sCsr1);
    cudaMemsetAsync(tot, 0, sizeof(int), sCsr1);
    k_count<<<e_grid, T, 0, sCsr1>>>(e0 + E, cnt, E);
    k_scanA<<<NB, SCAN_B, 0, sCsr1>>>(cnt, off, cur, dinv, tot, N);
    k_fill<<<e_grid, T, 0, sCsr1>>>(e0, e0 + E, cur, csr, E);
    cudaEventRecord(evCsr1, sCsr1);

    // -------- main: epilogue + aggregate (joins CSR1) --------
    cudaStreamWaitEvent(0, evCsr1, 0);
    k_epilogue<<<ep_grid, T>>>(h, dinv, b1, hsh, agg, N);
    k_aggregate<<<ag_grid, T>>>(csr, off, cnt, dinv, hsh, agg, N);

    // -------- sCsr2: layer-2 CSR build (independent; overlaps everything) --------
    cudaStreamWaitEvent(sCsr2, evFork, 0);
    cudaMemsetAsync(cnt2, 0, N * sizeof(int), sCsr2);
    cudaMemsetAsync(tot2, 0, sizeof(int), sCsr2);
    k_count<<<e_grid, T, 0, sCsr2>>>(e1 + E, cnt2, E);
    k_scanA<<<NB, SCAN_B, 0, sCsr2>>>(cnt2, off2, cur2, dinv2, tot2, N);
    k_fill<<<e_grid, T, 0, sCsr2>>>(e1, e1 + E, cur2, csr2, E);
    cudaEventRecord(evCsr2, sCsr2);

    // -------- main: layer 2 (fused epilogue; ReLU on input) --------
    cudaStreamWaitEvent(0, evCsr2, 0);
    k_gemm_fused<<<gm_grid, 256, gm_smem>>>(agg, W2, b2, dinv2, hsh, out, N, 1, 1);
    k_aggregate<<<ag_grid, T>>>(csr2, off2, cnt2, dinv2, hsh, out, N);
}

// round 15
// speedup vs baseline: 1.4750x; 1.4750x over previous
#include <cuda_runtime.h>
#include <cuda_fp16.h>

#define NMAX 100000
#define EMAX 3200000
#define DD 64
#define CAP 96
#define OVFMAX 65536

// Scratch (device globals; allocation is forbidden). Single CSR set, reused
// serially by both layers.
__device__ float  g_dinv[NMAX];
__device__ int    g_cur[NMAX];          // fill cursor; afterwards = edge count
__device__ int    g_csr[NMAX * CAP];    // bucketed CSR: node i owns [i*CAP, i*CAP+CAP)
__device__ int    g_ovf_cnt[1];
__device__ int2   g_ovf[OVFMAX];

__device__ __half2 g_hsh[NMAX * 32];    // h*dinv[row], fp16, 32 half2 per row
__device__ float  g_agg[NMAX * DD];     // layer-1 output (self+bias, then += messages)

// ---------------------------------------------------------------------------
// Direct bucketed fill: no count, no scan. p = cursor slot for this edge.
__global__ void k_fill(const int* __restrict__ src, const int* __restrict__ dst,
                       int* __restrict__ cur, int* __restrict__ csr,
                       int* __restrict__ ovf_cnt, int2* __restrict__ ovf, int ne) {
    int i = blockIdx.x * blockDim.x + threadIdx.x;
    if (i >= ne) return;
    int d = __ldg(dst + i);
    int s = __ldg(src + i);
    int p = atomicAdd(cur + d, 1);
    if (p < CAP) {
        csr[d * CAP + p] = s;
    } else {
        int q = atomicAdd(ovf_cnt, 1);
        if (q < OVFMAX) ovf[q] = make_int2(s, d);
    }
}

// dinv[i] = rsqrt(deg), deg = cnt + 1 (self loop)
__global__ void k_dinv(const int* __restrict__ cur, float* __restrict__ dinv, int n) {
    int i = blockIdx.x * blockDim.x + threadIdx.x;
    if (i < n) dinv[i] = rsqrtf((float)cur[i] + 1.0f);
}

// ---------------------------------------------------------------------------
// Register-tiled GEMM + fused epilogue.
//   h   = f(in) @ W        (f = identity or ReLU)
//   hsh = fp16(h * dinv[row])          -> message features for gather
//   agg = h * dinv^2 + b   (fp32)      -> self-loop + bias (output init)
#define XPAD 68
__global__ __launch_bounds__(256, 2)
void k_gemm_fused(const float* __restrict__ in, const float* __restrict__ W,
                  const float* __restrict__ b, const float* __restrict__ dinv,
                  __half2* __restrict__ hsh, float* __restrict__ agg,
                  int n, int do_relu) {
    extern __shared__ float smem_f[];
    float* Ws = smem_f;                 // 64*64
    float* xs = smem_f + DD * DD;       // 256*XPAD

    int tid = threadIdx.x;
    int cx = tid & 15;
    int ry = tid >> 4;
    int row0 = blockIdx.x * 256;

    for (int i = tid; i < DD * DD; i += 256) Ws[i] = W[i];

    for (int i = tid; i < 256 * 16; i += 256) {
        int r = i >> 4, c4 = i & 15;
        int grow = row0 + r;
        float4 v = make_float4(0.f, 0.f, 0.f, 0.f);
        if (grow < n) v = __ldg(reinterpret_cast<const float4*>(in + (size_t)grow * DD) + c4);
        if (do_relu) {
            v.x = fmaxf(v.x, 0.f); v.y = fmaxf(v.y, 0.f);
            v.z = fmaxf(v.z, 0.f); v.w = fmaxf(v.w, 0.f);
        }
        *reinterpret_cast<float4*>(&xs[r * XPAD + c4 * 4]) = v;
    }
    __syncthreads();

    float4 acc[16];
#pragma unroll
    for (int i = 0; i < 16; i++) acc[i] = make_float4(0.f, 0.f, 0.f, 0.f);

#pragma unroll
    for (int k4 = 0; k4 < 16; k4++) {
        float4 w0 = *reinterpret_cast<const float4*>(&Ws[(k4 * 4 + 0) * DD + cx * 4]);
        float4 w1 = *reinterpret_cast<const float4*>(&Ws[(k4 * 4 + 1) * DD + cx * 4]);
        float4 w2 = *reinterpret_cast<const float4*>(&Ws[(k4 * 4 + 2) * DD + cx * 4]);
        float4 w3 = *reinterpret_cast<const float4*>(&Ws[(k4 * 4 + 3) * DD + cx * 4]);
#pragma unroll
        for (int i = 0; i < 16; i++) {
            float4 xv = *reinterpret_cast<const float4*>(&xs[(ry + 16 * i) * XPAD + k4 * 4]);
            acc[i].x = fmaf(w0.x, xv.x, acc[i].x);
            acc[i].y = fmaf(w0.y, xv.x, acc[i].y);
            acc[i].z = fmaf(w0.z, xv.x, acc[i].z);
            acc[i].w = fmaf(w0.w, xv.x, acc[i].w);
            acc[i].x = fmaf(w1.x, xv.y, acc[i].x);
            acc[i].y = fmaf(w1.y, xv.y, acc[i].y);
            acc[i].z = fmaf(w1.z, xv.y, acc[i].z);
            acc[i].w = fmaf(w1.w, xv.y, acc[i].w);
            acc[i].x = fmaf(w2.x, xv.z, acc[i].x);
            acc[i].y = fmaf(w2.y, xv.z, acc[i].y);
            acc[i].z = fmaf(w2.z, xv.z, acc[i].z);
            acc[i].w = fmaf(w2.w, xv.z, acc[i].w);
            acc[i].x = fmaf(w3.x, xv.w, acc[i].x);
            acc[i].y = fmaf(w3.y, xv.w, acc[i].y);
            acc[i].z = fmaf(w3.z, xv.w, acc[i].z);
            acc[i].w = fmaf(w3.w, xv.w, acc[i].w);
        }
    }

    float4 bv = __ldg(reinterpret_cast<const float4*>(b) + cx);
#pragma unroll
    for (int i = 0; i < 16; i++) {
        int grow = row0 + ry + 16 * i;
        if (grow >= n) continue;
        float di = __ldg(dinv + grow);
        float4 h4 = acc[i];
        float4 hs4 = make_float4(h4.x * di, h4.y * di, h4.z * di, h4.w * di);
        float4 ag4 = make_float4(fmaf(hs4.x, di, bv.x), fmaf(hs4.y, di, bv.y),
                                 fmaf(hs4.z, di, bv.z), fmaf(hs4.w, di, bv.w));
        __half2 p0 = __floats2half2_rn(hs4.x, hs4.y);
        __half2 p1 = __floats2half2_rn(hs4.z, hs4.w);
        uint2 packed;
        packed.x = *reinterpret_cast<unsigned int*>(&p0);
        packed.y = *reinterpret_cast<unsigned int*>(&p1);
        *reinterpret_cast<uint2*>(hsh + (size_t)grow * 32 + cx * 2) = packed;
        *reinterpret_cast<float4*>(agg + (size_t)grow * DD + cx * 4) = ag4;
    }
}

// ---------------------------------------------------------------------------
// Gather-by-destination: one warp per node, two edges per warp-step.
// Half-warp h (=lane>>4) processes edges of parity h; lane sub (=lane&15) owns
// columns [4*sub, 4*sub+3] via one uint2 (= 4 fp16) load per edge.
__global__ __launch_bounds__(256)
void k_aggregate(const int* __restrict__ csr, const int* __restrict__ cnt,
                 const float* __restrict__ dinv, const __half2* __restrict__ hsh,
                 float* __restrict__ out, int n) {
    int node = blockIdx.x * 8 + (threadIdx.x >> 5);
    int lane = threadIdx.x & 31;
    if (node >= n) return;

    const unsigned FULL = 0xffffffffu;
    int half = lane >> 4;
    int sub  = lane & 15;
    int beg = node * CAP;
    int m = cnt[node];
    if (m > CAP) m = CAP;           // overflow edges handled by k_overflow
    float nd = dinv[node];

    float4 acc = make_float4(0.f, 0.f, 0.f, 0.f);

    int j = 0;
    while (j < m) {
        int rem = m - j;
        int myidx = (lane < rem) ? __ldg(csr + beg + j + lane) : 0;
        int lim = rem < 32 ? rem : 32;
        int t = 0;
        for (; t + 4 <= lim; t += 4) {
            int sa = __shfl_sync(FULL, myidx, t + half);
            int sb = __shfl_sync(FULL, myidx, t + 2 + half);
            uint2 va = __ldg(reinterpret_cast<const uint2*>(hsh + (size_t)sa * 32) + sub);
            uint2 vb = __ldg(reinterpret_cast<const uint2*>(hsh + (size_t)sb * 32) + sub);
            float2 a0 = __half22float2(*reinterpret_cast<__half2*>(&va.x));
            float2 a1 = __half22float2(*reinterpret_cast<__half2*>(&va.y));
            float2 b0 = __half22float2(*reinterpret_cast<__half2*>(&vb.x));
            float2 b1 = __half22float2(*reinterpret_cast<__half2*>(&vb.y));
            acc.x += a0.x + b0.x;
            acc.y += a0.y + b0.y;
            acc.z += a1.x + b1.x;
            acc.w += a1.y + b1.y;
        }
        for (; t < lim; t += 2) {
            int eid = t + half;
            int s = __shfl_sync(FULL, myidx, (eid < lim) ? eid : 0);
            if (eid < lim) {
                uint2 v = __ldg(reinterpret_cast<const uint2*>(hsh + (size_t)s * 32) + sub);
                float2 f0 = __half22float2(*reinterpret_cast<__half2*>(&v.x));
                float2 f1 = __half22float2(*reinterpret_cast<__half2*>(&v.y));
                acc.x += f0.x; acc.y += f0.y; acc.z += f1.x; acc.w += f1.y;
            }
        }
        j += 32;
    }

    acc.x += __shfl_xor_sync(FULL, acc.x, 16);
    acc.y += __shfl_xor_sync(FULL, acc.y, 16);
    acc.z += __shfl_xor_sync(FULL, acc.z, 16);
    acc.w += __shfl_xor_sync(FULL, acc.w, 16);

    if (half == 0) {
        float4* op = reinterpret_cast<float4*>(out + (size_t)node * DD + sub * 4);
        float4 o = *op;
        o.x = fmaf(acc.x, nd, o.x);
        o.y = fmaf(acc.y, nd, o.y);
        o.z = fmaf(acc.z, nd, o.z);
        o.w = fmaf(acc.w, nd, o.w);
        *op = o;
    }
}

// ---------------------------------------------------------------------------
// Overflow edges (deg > CAP; essentially never fires for this input, but keeps
// the kernel correct for arbitrary inputs). Atomic fp32 scatter from fp16 hsh.
// Runs AFTER k_aggregate in stream order, so RED vs plain-RMW never overlap.
__global__ void k_overflow(const int2* __restrict__ ovf, const int* __restrict__ ovf_cnt,
                           const float* __restrict__ dinv, const __half2* __restrict__ hsh,
                           float* __restrict__ out) {
    int total = *ovf_cnt;
    if (total > OVFMAX) total = OVFMAX;
    int work = total * 16;
    for (int t = blockIdx.x * blockDim.x + threadIdx.x; t < work;
         t += gridDim.x * blockDim.x) {
        int e = t >> 4, lane = t & 15;
        int2 ed = ovf[e];
        float norm = __ldg(dinv + ed.y);
        uint2 v = __ldg(reinterpret_cast<const uint2*>(hsh + (size_t)ed.x * 32) + lane);
        float2 f0 = __half22float2(*reinterpret_cast<__half2*>(&v.x));
        float2 f1 = __half22float2(*reinterpret_cast<__half2*>(&v.y));
        float* op = out + (size_t)ed.y * DD + lane * 4;
        asm volatile("red.global.add.v4.f32 [%0], {%1,%2,%3,%4};"
                     :: "l"(op), "f"(f0.x * norm), "f"(f0.y * norm),
                        "f"(f1.x * norm), "f"(f1.y * norm) : "memory");
    }
}

// ---------------------------------------------------------------------------
static void* sym_addr(const void* sym) {
    void* p = nullptr;
    cudaGetSymbolAddress(&p, sym);
    return p;
}

extern "C" void kernel_launch(void* const* d_in, const int* in_sizes, int n_in,
                              void* d_out, int out_size) {
    const float* x  = (const float*)d_in[0];
    const float* W1 = (const float*)d_in[1];
    const float* b1 = (const float*)d_in[2];
    const float* W2 = (const float*)d_in[3];
    const float* b2 = (const float*)d_in[4];
    const int*   e0 = (const int*)d_in[5];   // [2, E]: src row then dst row
    const int*   e1 = (const int*)d_in[6];

    const int N = in_sizes[0] / DD;
    const int E = in_sizes[5] / 2;

    float*  dinv = (float*)sym_addr(g_dinv);
    int*    cur  = (int*)sym_addr(g_cur);
    int*    csr  = (int*)sym_addr(g_csr);
    int*    ovfc = (int*)sym_addr(g_ovf_cnt);
    int2*   ovf  = (int2*)sym_addr(g_ovf);
    __half2* hsh = (__half2*)sym_addr(g_hsh);
    float*  agg  = (float*)sym_addr(g_agg);
    float*  out  = (float*)d_out;

    const int T = 256;
    int n_grid  = (N + T - 1) / T;
    int e_grid  = (E + T - 1) / T;
    int ag_grid = (N + 7) / 8;
    int gm_grid = (N + 255) / 256;
    size_t gm_smem = (DD * DD + 256 * XPAD) * sizeof(float);

    static int init_done = 0;
    if (!init_done) {
        cudaFuncSetAttribute(k_gemm_fused, cudaFuncAttributeMaxDynamicSharedMemorySize,
                             (int)gm_smem);
        init_done = 1;
    }

    // ---------------- Layer 1 (fully serial, single stream) ----------------
    cudaMemsetAsync(cur, 0, N * sizeof(int));
    cudaMemsetAsync(ovfc, 0, sizeof(int));
    k_fill<<<e_grid, T>>>(e0, e0 + E, cur, csr, ovfc, ovf, E);
    k_dinv<<<n_grid, T>>>(cur, dinv, N);
    k_gemm_fused<<<gm_grid, 256, gm_smem>>>(x, W1, b1, dinv, hsh, agg, N, 0);
    k_aggregate<<<ag_grid, T>>>(csr, cur, dinv, hsh, agg, N);
    k_overflow<<<32, T>>>(ovf, ovfc, dinv, hsh, agg);

    // ---------------- Layer 2 ----------------
    cudaMemsetAsync(cur, 0, N * sizeof(int));
    cudaMemsetAsync(ovfc, 0, sizeof(int));
    k_fill<<<e_grid, T>>>(e1, e1 + E, cur, csr, ovfc, ovf, E);
    k_dinv<<<n_grid, T>>>(cur, dinv, N);
    k_gemm_fused<<<gm_grid, 256, gm_smem>>>(agg, W2, b2, dinv, hsh, out, N, 1);  // ReLU fused
    k_aggregate<<<ag_grid, T>>>(csr, cur, dinv, hsh, out, N);
    k_overflow<<<32, T>>>(ovf, ovfc, dinv, hsh, out);
}

// round 16
// speedup vs baseline: 1.6550x; 1.1220x over previous
#include <cuda_runtime.h>
#include <cuda_fp16.h>

#define NMAX 100000
#define EMAX 3200000
#define DD 64
#define CAP 96
#define OVFMAX 65536

// Scratch (device globals; allocation is forbidden). Single CSR set, reused
// serially by both layers.
__device__ float  g_dinv[NMAX];
__device__ int    g_cur[NMAX];          // fill cursor; afterwards = edge count
__device__ int    g_csr[NMAX * CAP];    // bucketed CSR: node i owns [i*CAP, i*CAP+CAP)
__device__ int    g_ovf_cnt[1];
__device__ int2   g_ovf[OVFMAX];

__device__ __half2 g_hsh[NMAX * 32];    // h*dinv[row], fp16, 32 half2 per row
__device__ float  g_agg[NMAX * DD];     // layer-1 output (self+bias, then += messages)

// ---------------------------------------------------------------------------
// Direct bucketed fill: no count, no scan. p = cursor slot for this edge.
__global__ void k_fill(const int* __restrict__ src, const int* __restrict__ dst,
                       int* __restrict__ cur, int* __restrict__ csr,
                       int* __restrict__ ovf_cnt, int2* __restrict__ ovf, int ne) {
    int i = blockIdx.x * blockDim.x + threadIdx.x;
    if (i >= ne) return;
    int d = __ldg(dst + i);
    int s = __ldg(src + i);
    int p = atomicAdd(cur + d, 1);
    if (p < CAP) {
        csr[d * CAP + p] = s;
    } else {
        int q = atomicAdd(ovf_cnt, 1);
        if (q < OVFMAX) ovf[q] = make_int2(s, d);
    }
}

// dinv[i] = rsqrt(deg), deg = cnt + 1 (self loop)
__global__ void k_dinv(const int* __restrict__ cur, float* __restrict__ dinv, int n) {
    int i = blockIdx.x * blockDim.x + threadIdx.x;
    if (i < n) dinv[i] = rsqrtf((float)cur[i] + 1.0f);
}

// ---------------------------------------------------------------------------
// Register-tiled GEMM + fused epilogue.
//   h   = f(in) @ W        (f = identity or ReLU)
//   hsh = fp16(h * dinv[row])          -> message features for gather
//   agg = h * dinv^2 + b   (fp32)      -> self-loop + bias (output init)
#define XPAD 68
__global__ __launch_bounds__(256, 2)
void k_gemm_fused(const float* __restrict__ in, const float* __restrict__ W,
                  const float* __restrict__ b, const float* __restrict__ dinv,
                  __half2* __restrict__ hsh, float* __restrict__ agg,
                  int n, int do_relu) {
    extern __shared__ float smem_f[];
    float* Ws = smem_f;                 // 64*64
    float* xs = smem_f + DD * DD;       // 256*XPAD

    int tid = threadIdx.x;
    int cx = tid & 15;
    int ry = tid >> 4;
    int row0 = blockIdx.x * 256;

    for (int i = tid; i < DD * DD; i += 256) Ws[i] = W[i];

    for (int i = tid; i < 256 * 16; i += 256) {
        int r = i >> 4, c4 = i & 15;
        int grow = row0 + r;
        float4 v = make_float4(0.f, 0.f, 0.f, 0.f);
        if (grow < n) v = __ldg(reinterpret_cast<const float4*>(in + (size_t)grow * DD) + c4);
        if (do_relu) {
            v.x = fmaxf(v.x, 0.f); v.y = fmaxf(v.y, 0.f);
            v.z = fmaxf(v.z, 0.f); v.w = fmaxf(v.w, 0.f);
        }
        *reinterpret_cast<float4*>(&xs[r * XPAD + c4 * 4]) = v;
    }
    __syncthreads();

    float4 acc[16];
#pragma unroll
    for (int i = 0; i < 16; i++) acc[i] = make_float4(0.f, 0.f, 0.f, 0.f);

#pragma unroll
    for (int k4 = 0; k4 < 16; k4++) {
        float4 w0 = *reinterpret_cast<const float4*>(&Ws[(k4 * 4 + 0) * DD + cx * 4]);
        float4 w1 = *reinterpret_cast<const float4*>(&Ws[(k4 * 4 + 1) * DD + cx * 4]);
        float4 w2 = *reinterpret_cast<const float4*>(&Ws[(k4 * 4 + 2) * DD + cx * 4]);
        float4 w3 = *reinterpret_cast<const float4*>(&Ws[(k4 * 4 + 3) * DD + cx * 4]);
#pragma unroll
        for (int i = 0; i < 16; i++) {
            float4 xv = *reinterpret_cast<const float4*>(&xs[(ry + 16 * i) * XPAD + k4 * 4]);
            acc[i].x = fmaf(w0.x, xv.x, acc[i].x);
            acc[i].y = fmaf(w0.y, xv.x, acc[i].y);
            acc[i].z = fmaf(w0.z, xv.x, acc[i].z);
            acc[i].w = fmaf(w0.w, xv.x, acc[i].w);
            acc[i].x = fmaf(w1.x, xv.y, acc[i].x);
            acc[i].y = fmaf(w1.y, xv.y, acc[i].y);
            acc[i].z = fmaf(w1.z, xv.y, acc[i].z);
            acc[i].w = fmaf(w1.w, xv.y, acc[i].w);
            acc[i].x = fmaf(w2.x, xv.z, acc[i].x);
            acc[i].y = fmaf(w2.y, xv.z, acc[i].y);
            acc[i].z = fmaf(w2.z, xv.z, acc[i].z);
            acc[i].w = fmaf(w2.w, xv.z, acc[i].w);
            acc[i].x = fmaf(w3.x, xv.w, acc[i].x);
            acc[i].y = fmaf(w3.y, xv.w, acc[i].y);
            acc[i].z = fmaf(w3.z, xv.w, acc[i].z);
            acc[i].w = fmaf(w3.w, xv.w, acc[i].w);
        }
    }

    float4 bv = __ldg(reinterpret_cast<const float4*>(b) + cx);
#pragma unroll
    for (int i = 0; i < 16; i++) {
        int grow = row0 + ry + 16 * i;
        if (grow >= n) continue;
        float di = __ldg(dinv + grow);
        float4 h4 = acc[i];
        float4 hs4 = make_float4(h4.x * di, h4.y * di, h4.z * di, h4.w * di);
        float4 ag4 = make_float4(fmaf(hs4.x, di, bv.x), fmaf(hs4.y, di, bv.y),
                                 fmaf(hs4.z, di, bv.z), fmaf(hs4.w, di, bv.w));
        __half2 p0 = __floats2half2_rn(hs4.x, hs4.y);
        __half2 p1 = __floats2half2_rn(hs4.z, hs4.w);
        uint2 packed;
        packed.x = *reinterpret_cast<unsigned int*>(&p0);
        packed.y = *reinterpret_cast<unsigned int*>(&p1);
        *reinterpret_cast<uint2*>(hsh + (size_t)grow * 32 + cx * 2) = packed;
        *reinterpret_cast<float4*>(agg + (size_t)grow * DD + cx * 4) = ag4;
    }
}

// ---------------------------------------------------------------------------
__device__ __forceinline__ __half2 u2h(unsigned int u) {
    return *reinterpret_cast<__half2*>(&u);
}

// Gather-by-destination: one warp per node, EIGHT edges per warp-step
// (4 per half-warp). fp16 HADD2 tree over the 4 edges, then one fp32 flush.
// Half-warp h (=lane>>4) takes edges {t+h, t+2+h, t+4+h, t+6+h}; lane sub
// (=lane&15) owns columns [4*sub, 4*sub+3] via one uint2 load per edge.
__global__ __launch_bounds__(256)
void k_aggregate(const int* __restrict__ csr, const int* __restrict__ cnt,
                 const float* __restrict__ dinv, const __half2* __restrict__ hsh,
                 float* __restrict__ out, int n) {
    int node = blockIdx.x * 8 + (threadIdx.x >> 5);
    int lane = threadIdx.x & 31;
    if (node >= n) return;

    const unsigned FULL = 0xffffffffu;
    int half = lane >> 4;
    int sub  = lane & 15;
    int beg = node * CAP;
    int m = cnt[node];
    if (m > CAP) m = CAP;           // overflow edges handled by k_overflow
    float nd = dinv[node];

    float4 acc = make_float4(0.f, 0.f, 0.f, 0.f);

    for (int j = 0; j < m; j += 32) {
        int rem = m - j;
        int lim = rem < 32 ? rem : 32;
        int myidx = (lane < lim) ? __ldg(csr + beg + j + lane) : 0;
        for (int t = 0; t < lim; t += 8) {
            int e0 = t + half;
            int e1 = t + 2 + half;
            int e2 = t + 4 + half;
            int e3 = t + 6 + half;
            int s0 = __shfl_sync(FULL, myidx, e0);
            int s1 = __shfl_sync(FULL, myidx, e1);
            int s2 = __shfl_sync(FULL, myidx, e2);
            int s3 = __shfl_sync(FULL, myidx, e3);
            uint2 v0 = make_uint2(0u, 0u), v1 = make_uint2(0u, 0u);
            uint2 v2 = make_uint2(0u, 0u), v3 = make_uint2(0u, 0u);
            if (e0 < lim) v0 = __ldg(reinterpret_cast<const uint2*>(hsh + (size_t)s0 * 32) + sub);
            if (e1 < lim) v1 = __ldg(reinterpret_cast<const uint2*>(hsh + (size_t)s1 * 32) + sub);
            if (e2 < lim) v2 = __ldg(reinterpret_cast<const uint2*>(hsh + (size_t)s2 * 32) + sub);
            if (e3 < lim) v3 = __ldg(reinterpret_cast<const uint2*>(hsh + (size_t)s3 * 32) + sub);
            // fp16 tree over the 4 edges (partials <= 4 message magnitudes)
            __half2 sx = __hadd2(__hadd2(u2h(v0.x), u2h(v1.x)),
                                 __hadd2(u2h(v2.x), u2h(v3.x)));
            __half2 sy = __hadd2(__hadd2(u2h(v0.y), u2h(v1.y)),
                                 __hadd2(u2h(v2.y), u2h(v3.y)));
            float2 fx = __half22float2(sx);
            float2 fy = __half22float2(sy);
            acc.x += fx.x; acc.y += fx.y; acc.z += fy.x; acc.w += fy.y;
        }
    }

    acc.x += __shfl_xor_sync(FULL, acc.x, 16);
    acc.y += __shfl_xor_sync(FULL, acc.y, 16);
    acc.z += __shfl_xor_sync(FULL, acc.z, 16);
    acc.w += __shfl_xor_sync(FULL, acc.w, 16);

    if (half == 0) {
        float4* op = reinterpret_cast<float4*>(out + (size_t)node * DD + sub * 4);
        float4 o = *op;
        o.x = fmaf(acc.x, nd, o.x);
        o.y = fmaf(acc.y, nd, o.y);
        o.z = fmaf(acc.z, nd, o.z);
        o.w = fmaf(acc.w, nd, o.w);
        *op = o;
    }
}

// ---------------------------------------------------------------------------
// Overflow edges (deg > CAP; essentially never fires for this input, but keeps
// the kernel correct for arbitrary inputs). Atomic fp32 scatter from fp16 hsh.
// Runs AFTER k_aggregate in stream order, so RED vs plain-RMW never overlap.
__global__ void k_overflow(const int2* __restrict__ ovf, const int* __restrict__ ovf_cnt,
                           const float* __restrict__ dinv, const __half2* __restrict__ hsh,
                           float* __restrict__ out) {
    int total = *ovf_cnt;
    if (total > OVFMAX) total = OVFMAX;
    int work = total * 16;
    for (int t = blockIdx.x * blockDim.x + threadIdx.x; t < work;
         t += gridDim.x * blockDim.x) {
        int e = t >> 4, lane = t & 15;
        int2 ed = ovf[e];
        float norm = __ldg(dinv + ed.y);
        uint2 v = __ldg(reinterpret_cast<const uint2*>(hsh + (size_t)ed.x * 32) + lane);
        float2 f0 = __half22float2(*reinterpret_cast<__half2*>(&v.x));
        float2 f1 = __half22float2(*reinterpret_cast<__half2*>(&v.y));
        float* op = out + (size_t)ed.y * DD + lane * 4;
        asm volatile("red.global.add.v4.f32 [%0], {%1,%2,%3,%4};"
                     :: "l"(op), "f"(f0.x * norm), "f"(f0.y * norm),
                        "f"(f1.x * norm), "f"(f1.y * norm) : "memory");
    }
}

// ---------------------------------------------------------------------------
static void* sym_addr(const void* sym) {
    void* p = nullptr;
    cudaGetSymbolAddress(&p, sym);
    return p;
}

extern "C" void kernel_launch(void* const* d_in, const int* in_sizes, int n_in,
                              void* d_out, int out_size) {
    const float* x  = (const float*)d_in[0];
    const float* W1 = (const float*)d_in[1];
    const float* b1 = (const float*)d_in[2];
    const float* W2 = (const float*)d_in[3];
    const float* b2 = (const float*)d_in[4];
    const int*   e0 = (const int*)d_in[5];   // [2, E]: src row then dst row
    const int*   e1 = (const int*)d_in[6];

    const int N = in_sizes[0] / DD;
    const int E = in_sizes[5] / 2;

    float*  dinv = (float*)sym_addr(g_dinv);
    int*    cur  = (int*)sym_addr(g_cur);
    int*    csr  = (int*)sym_addr(g_csr);
    int*    ovfc = (int*)sym_addr(g_ovf_cnt);
    int2*   ovf  = (int2*)sym_addr(g_ovf);
    __half2* hsh = (__half2*)sym_addr(g_hsh);
    float*  agg  = (float*)sym_addr(g_agg);
    float*  out  = (float*)d_out;

    const int T = 256;
    int n_grid  = (N + T - 1) / T;
    int e_grid  = (E + T - 1) / T;
    int ag_grid = (N + 7) / 8;
    int gm_grid = (N + 255) / 256;
    size_t gm_smem = (DD * DD + 256 * XPAD) * sizeof(float);

    static int init_done = 0;
    if (!init_done) {
        cudaFuncSetAttribute(k_gemm_fused, cudaFuncAttributeMaxDynamicSharedMemorySize,
                             (int)gm_smem);
        init_done = 1;
    }

    // ---------------- Layer 1 (fully serial, single stream) ----------------
    cudaMemsetAsync(cur, 0, N * sizeof(int));
    cudaMemsetAsync(ovfc, 0, sizeof(int));
    k_fill<<<e_grid, T>>>(e0, e0 + E, cur, csr, ovfc, ovf, E);
    k_dinv<<<n_grid, T>>>(cur, dinv, N);
    k_gemm_fused<<<gm_grid, 256, gm_smem>>>(x, W1, b1, dinv, hsh, agg, N, 0);
    k_aggregate<<<ag_grid, T>>>(csr, cur, dinv, hsh, agg, N);
    k_overflow<<<32, T>>>(ovf, ovfc, dinv, hsh, agg);

    // ---------------- Layer 2 ----------------
    cudaMemsetAsync(cur, 0, N * sizeof(int));
    cudaMemsetAsync(ovfc, 0, sizeof(int));
    k_fill<<<e_grid, T>>>(e1, e1 + E, cur, csr, ovfc, ovf, E);
    k_dinv<<<n_grid, T>>>(cur, dinv, N);
    k_gemm_fused<<<gm_grid, 256, gm_smem>>>(agg, W2, b2, dinv, hsh, out, N, 1);  // ReLU fused
    k_aggregate<<<ag_grid, T>>>(csr, cur, dinv, hsh, out, N);
    k_overflow<<<32, T>>>(ovf, ovfc, dinv, hsh, out);
}